// round 1
// baseline (speedup 1.0000x reference)
#include <cuda_runtime.h>
#include <math.h>

#define BSZ 8192
#define DIM 128
#define TM 64
#define TN 64
#define PITCH 65          // pitch-65 k-major smem: conflict-free transposed stores
#define TINV 14.285714285714286f   // 1/0.07

__device__ double g_loss[2];      // [0]=loss1 (masked sim11), [1]=loss2 (sim12)
__device__ float  g_inv1[BSZ];
__device__ float  g_inv2[BSZ];

// One warp per row: sum of squares -> rsqrt. Also zeroes accumulators.
__global__ void norms_kernel(const float* __restrict__ e1,
                             const float* __restrict__ e2) {
    int warp = threadIdx.x >> 5;
    int lane = threadIdx.x & 31;
    int row  = blockIdx.x * 8 + warp;
    const float* src = (blockIdx.y == 0) ? e1 : e2;
    float4 v = ((const float4*)(src + (size_t)row * DIM))[lane];  // 32 lanes * 4 = 128
    float s = v.x * v.x + v.y * v.y + v.z * v.z + v.w * v.w;
    #pragma unroll
    for (int o = 16; o > 0; o >>= 1) s += __shfl_xor_sync(0xffffffffu, s, o);
    if (lane == 0) {
        float inv = rsqrtf(s);
        if (blockIdx.y == 0) g_inv1[row] = inv; else g_inv2[row] = inv;
    }
    if (blockIdx.x == 0 && blockIdx.y == 0 && threadIdx.x == 0) {
        g_loss[0] = 0.0;
        g_loss[1] = 0.0;
    }
}

// Tiled fp32 GEMM (64x64 tile, 4x4 micro-tile) with fused cosine+exp+reduce
// epilogue. blockIdx.z = 0: e1 x e1^T with mask ((k-i) mod B) > i  -> loss1
//           blockIdx.z = 1: e1 x e2^T (all pairs)                  -> loss2
__global__ __launch_bounds__(256) void tile_kernel(const float* __restrict__ e1,
                                                   const float* __restrict__ e2) {
    extern __shared__ float smem[];
    float* As = smem;                 // [DIM][PITCH], k-major
    float* Bs = smem + DIM * PITCH;   // [DIM][PITCH], k-major

    const int z  = blockIdx.z;
    const int i0 = blockIdx.y * TM;   // rows, always from e1
    const int k0 = blockIdx.x * TN;   // cols, e1 (z=0) or e2 (z=1)
    const float* Bp = z ? e2 : e1;

    const int tid = threadIdx.x;

    // Cooperative load: 64 rows x 32 float4 per tile, transposed into k-major smem.
    #pragma unroll
    for (int t = 0; t < 8; t++) {
        int l  = tid + t * 256;       // 0..2047
        int r  = l >> 5;              // row within tile
        int c4 = l & 31;              // float4 index along k
        int kk = c4 * 4;
        float4 va = ((const float4*)(e1 + (size_t)(i0 + r) * DIM))[c4];
        As[(kk + 0) * PITCH + r] = va.x;
        As[(kk + 1) * PITCH + r] = va.y;
        As[(kk + 2) * PITCH + r] = va.z;
        As[(kk + 3) * PITCH + r] = va.w;
        float4 vb = ((const float4*)(Bp + (size_t)(k0 + r) * DIM))[c4];
        Bs[(kk + 0) * PITCH + r] = vb.x;
        Bs[(kk + 1) * PITCH + r] = vb.y;
        Bs[(kk + 2) * PITCH + r] = vb.z;
        Bs[(kk + 3) * PITCH + r] = vb.w;
    }
    __syncthreads();

    const int tx = tid & 15;          // 16 col-groups
    const int ty = tid >> 4;          // 16 row-groups
    const float* Arow = As + ty * 4;
    const float* Brow = Bs + tx * 4;

    float acc[4][4];
    #pragma unroll
    for (int m = 0; m < 4; m++)
        #pragma unroll
        for (int n = 0; n < 4; n++) acc[m][n] = 0.0f;

    #pragma unroll 8
    for (int k = 0; k < DIM; k++) {
        float a[4], b[4];
        #pragma unroll
        for (int m = 0; m < 4; m++) a[m] = Arow[k * PITCH + m];
        #pragma unroll
        for (int n = 0; n < 4; n++) b[n] = Brow[k * PITCH + n];
        #pragma unroll
        for (int m = 0; m < 4; m++)
            #pragma unroll
            for (int n = 0; n < 4; n++) acc[m][n] = fmaf(a[m], b[n], acc[m][n]);
    }

    // Epilogue: cosine normalize, optional mask, exp, local accumulate.
    float invA[4], invB[4];
    #pragma unroll
    for (int m = 0; m < 4; m++) invA[m] = g_inv1[i0 + ty * 4 + m];
    #pragma unroll
    for (int n = 0; n < 4; n++) invB[n] = (z ? g_inv2 : g_inv1)[k0 + tx * 4 + n];

    float local = 0.0f;
    #pragma unroll
    for (int m = 0; m < 4; m++) {
        int gi = i0 + ty * 4 + m;
        #pragma unroll
        for (int n = 0; n < 4; n++) {
            int gk = k0 + tx * 4 + n;
            float sim = acc[m][n] * (invA[m] * invB[n]);
            bool ok = z ? true : (((gk - gi + BSZ) & (BSZ - 1)) > gi);
            if (ok) local += __expf(sim * TINV);
        }
    }

    // Warp then block reduction, single double atomic per block.
    #pragma unroll
    for (int o = 16; o > 0; o >>= 1) local += __shfl_xor_sync(0xffffffffu, local, o);
    __shared__ float red[8];
    int lane = tid & 31, warp = tid >> 5;
    if (lane == 0) red[warp] = local;
    __syncthreads();
    if (tid == 0) {
        float s = 0.0f;
        #pragma unroll
        for (int w = 0; w < 8; w++) s += red[w];
        atomicAdd(&g_loss[z], (double)s);
    }
}

__global__ void final_kernel(float* __restrict__ out) {
    out[0] = (float)(-log(g_loss[0] / g_loss[1]));
}

extern "C" void kernel_launch(void* const* d_in, const int* in_sizes, int n_in,
                              void* d_out, int out_size) {
    const float* e1 = (const float*)d_in[0];
    const float* e2 = (const float*)d_in[1];
    float* out = (float*)d_out;

    norms_kernel<<<dim3(BSZ / 8, 2), 256>>>(e1, e2);

    size_t smem = (size_t)2 * DIM * PITCH * sizeof(float);  // 66560 B
    cudaFuncSetAttribute(tile_kernel,
                         cudaFuncAttributeMaxDynamicSharedMemorySize, (int)smem);
    tile_kernel<<<dim3(BSZ / TN, BSZ / TM, 2), 256, smem>>>(e1, e2);

    final_kernel<<<1, 1>>>(out);
}

// round 10
// speedup vs baseline: 6.1121x; 6.1121x over previous
#include <cuda_runtime.h>
#include <cuda_bf16.h>
#include <cstdint>
#include <math.h>

#define BSZ 8192
#define DIM 128
#define TM 128
#define TN 128
#define TINV 14.285714285714286f

// ---- device globals (no allocs allowed) ----
__device__ double g_partial[2][64];
__device__ __nv_bfloat16 g_b1[BSZ * DIM];   // normalized e1, bf16
__device__ __nv_bfloat16 g_b2[BSZ * DIM];   // normalized e2, bf16

__device__ __forceinline__ uint32_t smem_u32(const void* p) {
    uint32_t a;
    asm("{ .reg .u64 t; cvta.to.shared.u64 t, %1; cvt.u32.u64 %0, t; }" : "=r"(a) : "l"(p));
    return a;
}

__device__ __forceinline__ void ldsm_x4(uint32_t* r, uint32_t addr) {
    asm volatile("ldmatrix.sync.aligned.m8n8.x4.shared.b16 {%0,%1,%2,%3}, [%4];"
                 : "=r"(r[0]), "=r"(r[1]), "=r"(r[2]), "=r"(r[3]) : "r"(addr));
}

__device__ __forceinline__ void mma_16816(float* d, const uint32_t* a,
                                          uint32_t b0, uint32_t b1) {
    asm volatile(
        "mma.sync.aligned.m16n8k16.row.col.f32.bf16.bf16.f32 "
        "{%0,%1,%2,%3}, {%4,%5,%6,%7}, {%8,%9}, {%0,%1,%2,%3};"
        : "+f"(d[0]), "+f"(d[1]), "+f"(d[2]), "+f"(d[3])
        : "r"(a[0]), "r"(a[1]), "r"(a[2]), "r"(a[3]), "r"(b0), "r"(b1));
}

// Swizzled smem byte offset: row-major, 256B rows, 16B chunks, chunk ^= row&7.
__device__ __forceinline__ int soff(int row, int chunk) {
    return row * 256 + ((chunk ^ (row & 7)) << 4);
}

// ---- kernel 1: normalize rows in fp32, write bf16 copies, zero partials ----
__global__ void prep_kernel(const float* __restrict__ e1, const float* __restrict__ e2) {
    int warp = threadIdx.x >> 5, lane = threadIdx.x & 31;
    int row = blockIdx.x * 8 + warp;
    const float* src = blockIdx.y ? e2 : e1;
    __nv_bfloat16* dst = blockIdx.y ? g_b2 : g_b1;
    float4 v = ((const float4*)(src + (size_t)row * DIM))[lane];
    float s = v.x * v.x + v.y * v.y + v.z * v.z + v.w * v.w;
    #pragma unroll
    for (int o = 16; o > 0; o >>= 1) s += __shfl_xor_sync(0xffffffffu, s, o);
    float inv = rsqrtf(s);
    __nv_bfloat162 p0 = __float22bfloat162_rn(make_float2(v.x * inv, v.y * inv));
    __nv_bfloat162 p1 = __float22bfloat162_rn(make_float2(v.z * inv, v.w * inv));
    ((__nv_bfloat162*)(dst + (size_t)row * DIM))[lane * 2 + 0] = p0;
    ((__nv_bfloat162*)(dst + (size_t)row * DIM))[lane * 2 + 1] = p1;
    if (blockIdx.x == 0 && blockIdx.y == 0 && threadIdx.x < 128)
        ((double*)g_partial)[threadIdx.x] = 0.0;
}

// ---- kernel 2: mma.sync bf16 tile GEMM + fused exp/mask/reduce epilogue ----
// CTA 128x128xK128; 8 warps in 4x2 grid, each 32(m) x 64(n).
#define SMEM_TOTAL (2 * TM * 256)

__global__ __launch_bounds__(256, 2) void tile_kernel() {
    extern __shared__ char smem[];
    const uint32_t sA = smem_u32(smem);
    const uint32_t sB = sA + TM * 256;
    const int tid = threadIdx.x;
    const int wid = tid >> 5, lane = tid & 31;

    const int z  = blockIdx.z;
    const int i0 = blockIdx.y * TM;
    const int k0 = blockIdx.x * TN;
    const __nv_bfloat16* Ap = g_b1 + (size_t)i0 * DIM;
    const __nv_bfloat16* Bp = (z ? g_b2 : g_b1) + (size_t)k0 * DIM;

    // Cooperative load: 128 rows x 16 chunks (uint4) per tile, swizzled.
    #pragma unroll
    for (int t = 0; t < 8; t++) {
        int l = tid + t * 256;          // 0..2047
        int r = l >> 4, c = l & 15;
        uint4 va = ((const uint4*)(Ap + (size_t)r * DIM))[c];
        *(uint4*)(smem + soff(r, c)) = va;
        uint4 vb = ((const uint4*)(Bp + (size_t)r * DIM))[c];
        *(uint4*)(smem + TM * 256 + soff(r, c)) = vb;
    }
    __syncthreads();

    const int wm = (wid & 3) * 32;      // warp m-base (4 warps down)
    const int wn = (wid >> 2) * 64;     // warp n-base (2 warps across)

    float acc[2][8][4];
    #pragma unroll
    for (int mi = 0; mi < 2; mi++)
        #pragma unroll
        for (int nj = 0; nj < 8; nj++)
            #pragma unroll
            for (int q = 0; q < 4; q++) acc[mi][nj][q] = 0.0f;

    #pragma unroll
    for (int kk = 0; kk < 8; kk++) {    // k-chunks of 16
        uint32_t a[2][4], b[4][4];
        // A: x4 ldmatrix covers 16(m) x 16(k). lanes 0-15 rows, lanes>>4 k-half.
        #pragma unroll
        for (int mi = 0; mi < 2; mi++) {
            int row = wm + mi * 16 + (lane & 15);
            int chunk = kk * 2 + (lane >> 4);
            ldsm_x4(a[mi], sA + soff(row, chunk));
        }
        // B: x4 covers 16(n) x 16(k): m0=(n0-7,k0) m1=(n0-7,k1) m2=(n8-15,k0) m3=(n8-15,k1)
        #pragma unroll
        for (int g = 0; g < 4; g++) {
            int row = wn + g * 16 + ((lane >> 4) << 3) + (lane & 7);
            int chunk = kk * 2 + ((lane >> 3) & 1);
            ldsm_x4(b[g], sB + soff(row, chunk));
        }
        #pragma unroll
        for (int mi = 0; mi < 2; mi++)
            #pragma unroll
            for (int nj = 0; nj < 8; nj++)
                mma_16816(acc[mi][nj], a[mi],
                          b[nj >> 1][(nj & 1) * 2], b[nj >> 1][(nj & 1) * 2 + 1]);
    }

    // Epilogue: exp(sim/T) with loss1 mask, accumulate locally.
    const int gID = lane >> 2, tig = lane & 3;
    float local = 0.0f;
    #pragma unroll
    for (int mi = 0; mi < 2; mi++) {
        #pragma unroll
        for (int nj = 0; nj < 8; nj++) {
            int gi0 = i0 + wm + mi * 16 + gID;
            int gk0 = k0 + wn + nj * 8 + 2 * tig;
            #pragma unroll
            for (int q = 0; q < 4; q++) {
                int gi = gi0 + (q >> 1) * 8;
                int gk = gk0 + (q & 1);
                float e = __expf(acc[mi][nj][q] * TINV);
                bool ok = z ? true : (((gk - gi) & (BSZ - 1)) > gi);
                local += ok ? e : 0.0f;
            }
        }
    }

    #pragma unroll
    for (int o = 16; o > 0; o >>= 1) local += __shfl_xor_sync(0xffffffffu, local, o);
    __shared__ float red[8];
    if (lane == 0) red[wid] = local;
    __syncthreads();
    if (tid == 0) {
        float s = 0.0f;
        #pragma unroll
        for (int w = 0; w < 8; w++) s += red[w];
        int slot = (blockIdx.x + blockIdx.y * 5) & 63;
        atomicAdd(&g_partial[z][slot], (double)s);
    }
}

__global__ void final_kernel(float* __restrict__ out) {
    double l1 = 0.0, l2 = 0.0;
    #pragma unroll
    for (int i = 0; i < 64; i++) { l1 += g_partial[0][i]; l2 += g_partial[1][i]; }
    out[0] = (float)(-log(l1 / l2));
}

extern "C" void kernel_launch(void* const* d_in, const int* in_sizes, int n_in,
                              void* d_out, int out_size) {
    const float* e1 = (const float*)d_in[0];
    const float* e2 = (const float*)d_in[1];
    float* out = (float*)d_out;

    prep_kernel<<<dim3(BSZ / 8, 2), 256>>>(e1, e2);

    cudaFuncSetAttribute(tile_kernel, cudaFuncAttributeMaxDynamicSharedMemorySize, SMEM_TOTAL);
    tile_kernel<<<dim3(BSZ / TN, BSZ / TM, 2), 256, SMEM_TOTAL>>>();

    final_kernel<<<1, 1>>>(out);
}

// round 11
// speedup vs baseline: 11.3909x; 1.8637x over previous
#include <cuda_runtime.h>
#include <cuda_bf16.h>
#include <cstdint>
#include <math.h>

#define BSZ 8192
#define DIM 128
#define TMM 128
#define TNN 256
#define NT0 2048          // z=0 tiles (64 x 32)
#define NTILES 4096
#define GRID 148
#define TINV 14.285714285714286f
#define STAGE 98304       // 96KB per stage: A 32KB + B 64KB
#define SMEM_TOTAL (2 * STAGE)

__device__ double g_partial[2][64];
__device__ __nv_bfloat16 g_b1[BSZ * DIM];
__device__ __nv_bfloat16 g_b2[BSZ * DIM];

__device__ __forceinline__ uint32_t smem_u32(const void* p) {
    uint32_t a;
    asm("{ .reg .u64 t; cvta.to.shared.u64 t, %1; cvt.u32.u64 %0, t; }" : "=r"(a) : "l"(p));
    return a;
}
__device__ __forceinline__ void ldsm_x4(uint32_t* r, uint32_t addr) {
    asm volatile("ldmatrix.sync.aligned.m8n8.x4.shared.b16 {%0,%1,%2,%3}, [%4];"
                 : "=r"(r[0]), "=r"(r[1]), "=r"(r[2]), "=r"(r[3]) : "r"(addr));
}
__device__ __forceinline__ void mma_16816(float* d, const uint32_t* a,
                                          uint32_t b0, uint32_t b1) {
    asm volatile(
        "mma.sync.aligned.m16n8k16.row.col.f32.bf16.bf16.f32 "
        "{%0,%1,%2,%3}, {%4,%5,%6,%7}, {%8,%9}, {%0,%1,%2,%3};"
        : "+f"(d[0]), "+f"(d[1]), "+f"(d[2]), "+f"(d[3])
        : "r"(a[0]), "r"(a[1]), "r"(a[2]), "r"(a[3]), "r"(b0), "r"(b1));
}
#define CP_ASYNC(dst, src) \
    asm volatile("cp.async.cg.shared.global [%0], [%1], 16;" :: "r"(dst), "l"(src) : "memory")
#define CP_COMMIT() asm volatile("cp.async.commit_group;" ::: "memory")
#define CP_WAIT(n)  asm volatile("cp.async.wait_group %0;" :: "n"(n) : "memory")

// Swizzled smem byte offset: 256B rows, 16B chunks, chunk ^= row&7.
__device__ __forceinline__ int soff(int row, int chunk) {
    return row * 256 + ((chunk ^ (row & 7)) << 4);
}

// ---- loss1 tile classification (rows r0..r0+127, cols c0..c0+255) ----
// excluded k-band per row i: [i, 2i] mod B  (contiguous, wraps for i >= B/2)
__device__ __forceinline__ bool tile_skip(int r0, int c0) {
    int r1 = r0 + 127, c1 = c0 + 255;
    if (r1 < BSZ / 2) return (c0 >= r1) && (c1 <= 2 * r0);
    return (c0 >= r1) || (c1 <= 2 * r0 - BSZ);
}
__device__ __forceinline__ bool tile_full(int r0, int c0) {
    int r1 = r0 + 127, c1 = c0 + 255;
    if (r1 < BSZ / 2) return (c1 < r0) || (c0 > 2 * r1);
    return (c0 > 2 * r1 - BSZ) && (c1 < r0);
}
__device__ __forceinline__ int next_tile(int t) {
    t += GRID;
    while (t < NT0 && tile_skip((t >> 5) * TMM, (t & 31) * TNN)) t += GRID;
    return t;
}

// ---- kernel 1: normalize rows in fp32, write bf16 copies, zero partials ----
__global__ void prep_kernel(const float* __restrict__ e1, const float* __restrict__ e2) {
    int warp = threadIdx.x >> 5, lane = threadIdx.x & 31;
    int row = blockIdx.x * 8 + warp;
    const float* src = blockIdx.y ? e2 : e1;
    __nv_bfloat16* dst = blockIdx.y ? g_b2 : g_b1;
    float4 v = ((const float4*)(src + (size_t)row * DIM))[lane];
    float s = v.x * v.x + v.y * v.y + v.z * v.z + v.w * v.w;
    #pragma unroll
    for (int o = 16; o > 0; o >>= 1) s += __shfl_xor_sync(0xffffffffu, s, o);
    float inv = rsqrtf(s);
    __nv_bfloat162 p0 = __float22bfloat162_rn(make_float2(v.x * inv, v.y * inv));
    __nv_bfloat162 p1 = __float22bfloat162_rn(make_float2(v.z * inv, v.w * inv));
    ((__nv_bfloat162*)(dst + (size_t)row * DIM))[lane * 2 + 0] = p0;
    ((__nv_bfloat162*)(dst + (size_t)row * DIM))[lane * 2 + 1] = p1;
    if (blockIdx.x == 0 && blockIdx.y == 0 && threadIdx.x < 128)
        ((double*)g_partial)[threadIdx.x] = 0.0;
}

// ---- prefetch one tile (A 128 rows + B 256 rows) via cp.async ----
__device__ __forceinline__ void prefetch_tile(int t, char* buf, int tid) {
    int z = t >= NT0;
    int tt = t & (NT0 - 1);
    const __nv_bfloat16* Ap = g_b1 + (size_t)((tt >> 5) * TMM) * DIM;
    const __nv_bfloat16* Bp = (z ? g_b2 : g_b1) + (size_t)((tt & 31) * TNN) * DIM;
    #pragma unroll
    for (int s = 0; s < 4; s++) {           // A: 2048 chunks
        int l = tid + s * 512, r = l >> 4, c = l & 15;
        CP_ASYNC(smem_u32(buf + soff(r, c)), (const void*)(Ap + (size_t)r * DIM + c * 8));
    }
    #pragma unroll
    for (int s = 0; s < 8; s++) {           // B: 4096 chunks
        int l = tid + s * 512, r = l >> 4, c = l & 15;
        CP_ASYNC(smem_u32(buf + 32768 + soff(r, c)), (const void*)(Bp + (size_t)r * DIM + c * 8));
    }
}

// ---- kernel 2: persistent double-buffered mma.sync GEMM + fused epilogue ----
// 512 threads, 16 warps in 4(m) x 4(n); warp tile 32 x 64; CTA tile 128 x 256.
__global__ __launch_bounds__(512, 1) void tile_kernel() {
    extern __shared__ char smem[];
    const int tid = threadIdx.x;
    const int wid = tid >> 5, lane = tid & 31;
    const int wm = (wid & 3) * 32, wn = (wid >> 2) * 64;

    int t = next_tile((int)blockIdx.x - GRID);   // first valid tile for this CTA
    if (t < NTILES) { prefetch_tile(t, smem, tid); }
    CP_COMMIT();

    float l1 = 0.0f, l2 = 0.0f;
    int cur = 0;

    while (t < NTILES) {
        int tn = next_tile(t);
        if (tn < NTILES) {
            prefetch_tile(tn, smem + (cur ^ 1) * STAGE, tid);
            CP_COMMIT();
            CP_WAIT(1);
        } else {
            CP_WAIT(0);
        }
        __syncthreads();

        const uint32_t sA = smem_u32(smem + cur * STAGE);
        const uint32_t sB = sA + 32768;
        const int z  = t >= NT0;
        const int tt = t & (NT0 - 1);
        const int i0 = (tt >> 5) * TMM;
        const int k0 = (tt & 31) * TNN;
        const bool need_mask = (z == 0) && !tile_full(i0, k0);

        float acc[2][8][4];
        #pragma unroll
        for (int mi = 0; mi < 2; mi++)
            #pragma unroll
            for (int nj = 0; nj < 8; nj++)
                #pragma unroll
                for (int q = 0; q < 4; q++) acc[mi][nj][q] = 0.0f;

        #pragma unroll
        for (int kk = 0; kk < 8; kk++) {
            uint32_t a[2][4], b[4][4];
            #pragma unroll
            for (int mi = 0; mi < 2; mi++) {
                int row = wm + mi * 16 + (lane & 15);
                int chunk = kk * 2 + (lane >> 4);
                ldsm_x4(a[mi], sA + soff(row, chunk));
            }
            #pragma unroll
            for (int g = 0; g < 4; g++) {
                int row = wn + g * 16 + ((lane >> 4) << 3) + (lane & 7);
                int chunk = kk * 2 + ((lane >> 3) & 1);
                ldsm_x4(b[g], sB + soff(row, chunk));
            }
            #pragma unroll
            for (int mi = 0; mi < 2; mi++)
                #pragma unroll
                for (int nj = 0; nj < 8; nj++)
                    mma_16816(acc[mi][nj], a[mi],
                              b[nj >> 1][(nj & 1) * 2], b[nj >> 1][(nj & 1) * 2 + 1]);
        }

        // Epilogue: exp(sim/T), optional band mask, accumulate in registers.
        const int gID = lane >> 2, tig = lane & 3;
        float local = 0.0f;
        if (need_mask) {
            #pragma unroll
            for (int mi = 0; mi < 2; mi++)
                #pragma unroll
                for (int nj = 0; nj < 8; nj++) {
                    int gi0 = i0 + wm + mi * 16 + gID;
                    int gk0 = k0 + wn + nj * 8 + 2 * tig;
                    #pragma unroll
                    for (int q = 0; q < 4; q++) {
                        int gi = gi0 + (q >> 1) * 8;
                        int gk = gk0 + (q & 1);
                        float e = __expf(acc[mi][nj][q] * TINV);
                        bool ok = (((gk - gi) & (BSZ - 1)) > gi);
                        local += ok ? e : 0.0f;
                    }
                }
        } else {
            #pragma unroll
            for (int mi = 0; mi < 2; mi++)
                #pragma unroll
                for (int nj = 0; nj < 8; nj++)
                    #pragma unroll
                    for (int q = 0; q < 4; q++)
                        local += __expf(acc[mi][nj][q] * TINV);
        }
        if (z) l2 += local; else l1 += local;

        __syncthreads();   // protect buf[cur] before next prefetch overwrites it
        cur ^= 1;
        t = tn;
    }

    // Final reduction: 2 atomics per CTA.
    #pragma unroll
    for (int o = 16; o > 0; o >>= 1) {
        l1 += __shfl_xor_sync(0xffffffffu, l1, o);
        l2 += __shfl_xor_sync(0xffffffffu, l2, o);
    }
    __shared__ float redA[16], redB[16];
    if (lane == 0) { redA[wid] = l1; redB[wid] = l2; }
    __syncthreads();
    if (tid == 0) {
        float s1 = 0.0f, s2 = 0.0f;
        #pragma unroll
        for (int w = 0; w < 16; w++) { s1 += redA[w]; s2 += redB[w]; }
        int slot = blockIdx.x & 63;
        atomicAdd(&g_partial[0][slot], (double)s1);
        atomicAdd(&g_partial[1][slot], (double)s2);
    }
}

__global__ void final_kernel(float* __restrict__ out) {
    double l1 = 0.0, l2 = 0.0;
    #pragma unroll
    for (int i = 0; i < 64; i++) { l1 += g_partial[0][i]; l2 += g_partial[1][i]; }
    out[0] = (float)(-log(l1 / l2));
}

extern "C" void kernel_launch(void* const* d_in, const int* in_sizes, int n_in,
                              void* d_out, int out_size) {
    const float* e1 = (const float*)d_in[0];
    const float* e2 = (const float*)d_in[1];
    float* out = (float*)d_out;

    prep_kernel<<<dim3(BSZ / 8, 2), 256>>>(e1, e2);

    cudaFuncSetAttribute(tile_kernel, cudaFuncAttributeMaxDynamicSharedMemorySize, SMEM_TOTAL);
    tile_kernel<<<GRID, 512, SMEM_TOTAL>>>();

    final_kernel<<<1, 1>>>(out);
}